// round 14
// baseline (speedup 1.0000x reference)
#include <cuda_runtime.h>
#include <cuda_bf16.h>
#include <math.h>
#include <float.h>
#include <stdint.h>

#define BTOT 8
#define SEQ  2048
#define MTOK (BTOT*SEQ)   /* 16384 */
#define DM   256
#define DQK  128
#define NH   8
#define DH   16
#define DV   32
#define NKNN 16
#define DFF  1024

// ---------------- scratch (static device globals; no allocations) ----------------
__device__ float  g_qk [MTOK*2*DQK];     // [tok][0:128]=qn, [128:256]=kn (f32)
__device__ float  g_kk [MTOK];
__device__ float2 g_part[MTOK*256];      // per-row 16 blockcols x 16 (dist,col)
__device__ int    g_idx[MTOK*NKNN];
__device__ float  g_y1 [MTOK*DM];
__device__ float  g_bqk[2*DQK];

// bf16 buffers (hi/lo pairs only where precision-critical)
__device__ __nv_bfloat16 g_u  [MTOK*DM];                  // value rows (bf16)
__device__ __nv_bfloat16 g_xh [MTOK*DM],  g_xl [MTOK*DM];
__device__ __nv_bfloat16 g_lnh[MTOK*DM];
__device__ __nv_bfloat16 g_qph[MTOK*DQK], g_qpl[MTOK*DQK];
__device__ __nv_bfloat16 g_kph[MTOK*DQK], g_kpl[MTOK*DQK];
__device__ __nv_bfloat16 g_oh [MTOK*DM];
__device__ __nv_bfloat16 g_hh [MTOK*DFF];
// transposed weights [N,K] bf16 (q|k keeps lo plane; value-path weights hi only)
__device__ __nv_bfloat16 g_wqkh[2*DQK*DM], g_wqkl[2*DQK*DM];
__device__ __nv_bfloat16 g_wvh[DM*DM];
__device__ __nv_bfloat16 g_woh[DM*DM];
__device__ __nv_bfloat16 g_w1h[DFF*DM];
__device__ __nv_bfloat16 g_w2h[DM*DFF];

// ---------------- PTX helpers -------------------------------------------------------
__device__ __forceinline__ uint32_t smem_u32(const void* p) {
    uint32_t a;
    asm("{ .reg .u64 t; cvta.to.shared.u64 t, %1; cvt.u32.u64 %0, t; }" : "=r"(a) : "l"(p));
    return a;
}
#define LDSM4(r0, r1, r2, r3, a) \
    asm volatile("ldmatrix.sync.aligned.m8n8.x4.shared.b16 {%0,%1,%2,%3}, [%4];" \
                 : "=r"(r0), "=r"(r1), "=r"(r2), "=r"(r3) : "r"(a))
#define MMA16816(c, a, b) \
    asm volatile("mma.sync.aligned.m16n8k16.row.col.f32.bf16.bf16.f32 " \
                 "{%0,%1,%2,%3}, {%4,%5,%6,%7}, {%8,%9}, {%0,%1,%2,%3};" \
                 : "+f"((c)[0]), "+f"((c)[1]), "+f"((c)[2]), "+f"((c)[3]) \
                 : "r"((a)[0]), "r"((a)[1]), "r"((a)[2]), "r"((a)[3]), \
                   "r"((b)[0]), "r"((b)[1]))
#define CP_COMMIT() asm volatile("cp.async.commit_group;" ::: "memory")
#define CP_WAIT1()  asm volatile("cp.async.wait_group 1;" ::: "memory")
#define CP_WAIT0()  asm volatile("cp.async.wait_group 0;" ::: "memory")

// SW64-style swizzle for 64-byte rows
__device__ __forceinline__ uint32_t swz64(uint32_t off) {
    return off ^ ((off >> 3) & 0x30);
}

// stage one 128x32-bf16 tile (64B rows) via cp.async, 256 threads, 2 segs each
__device__ __forceinline__ void stage32(uint32_t dst, const __nv_bfloat16* src,
                                        int ldK, int tid) {
#pragma unroll
    for (int j = 0; j < 2; j++) {
        int u = tid + j * 256;
        int row = u >> 2, seg = u & 3;
        uint32_t off = swz64((uint32_t)(row * 64 + seg * 16));
        const void* gp = (const void*)(src + (long long)row * ldK + seg * 8);
        asm volatile("cp.async.cg.shared.global [%0], [%1], 16;"
                     :: "r"(dst + off), "l"(gp) : "memory");
    }
}

// ---------------- bf16 mma.sync GEMM: C(128x128/blk) = A·Bᵀ, fp32 acc --------------
// A: [M,K] K-major bf16. B: [N,K] K-major bf16. K multiple of 32.
// NT = 3: bf16x3 (ah·bh + ah·bl + al·bh, precision path); NT = 1: plain bf16.
// EPI: 0 = acc+bias -> f32 ; 1 = fused knn: d2 = extra[col]-2*acc, per-row top-16
//      via smem (column-major, reuses staging) -> float2 partials (C) ;
//      2 = gelu(acc+bias) -> bf16 ; 3 = extra[row,col]+rw*(acc+bias) -> f32 ;
//      4 = acc+bias -> bf16
// R10-proven engine: 2-stage double buffer, per-f interleaved MMA.
#define TILEB 8192

template<int EPI, int NT>
__global__ void __launch_bounds__(256, 2)
mma_gemm(const __nv_bfloat16* __restrict__ Ah, const __nv_bfloat16* __restrict__ Al,
         const __nv_bfloat16* __restrict__ Bh, const __nv_bfloat16* __restrict__ Bl,
         const float* __restrict__ bias, float* __restrict__ C,
         __nv_bfloat16* __restrict__ Ch,
         int Kdim, int Ndim,
         const float* __restrict__ extra, const float* __restrict__ rwp,
         long long sAz, long long sBz, long long sCz, long long sEz)
{
    constexpr uint32_t BOFF = (NT == 3) ? 2 * TILEB : TILEB;       // B tile offset
    constexpr uint32_t STG  = (NT == 3) ? 4 * TILEB : 2 * TILEB;   // stage bytes

    extern __shared__ __align__(128) char smem[];
    const uint32_t sb = smem_u32(smem);
    const int tid = threadIdx.x, lane = tid & 31, wid = tid >> 5;
    const int wm = wid & 1, wn = wid >> 1;
    const int bz = blockIdx.z;
    Ah += bz * sAz; if (NT == 3) Al += bz * sAz;
    Bh += bz * sBz; if (NT == 3) Bl += bz * sBz;
    if (EPI == 0 || EPI == 1 || EPI == 3) C += bz * sCz;
    if (EPI == 1) extra += bz * sEz;
    const int m0 = blockIdx.y * 128, n0 = blockIdx.x * 128;

    const __nv_bfloat16* A0h = Ah + (long long)m0 * Kdim;
    const __nv_bfloat16* A0l = (NT == 3) ? (Al + (long long)m0 * Kdim) : nullptr;
    const __nv_bfloat16* B0h = Bh + (long long)n0 * Kdim;
    const __nv_bfloat16* B0l = (NT == 3) ? (Bl + (long long)n0 * Kdim) : nullptr;

    float acc[4][4][4];
#pragma unroll
    for (int f = 0; f < 4; f++)
#pragma unroll
        for (int j = 0; j < 4; j++)
#pragma unroll
            for (int e = 0; e < 4; e++) acc[f][j][e] = 0.0f;

    const int nch = Kdim >> 5;

    {
        stage32(sb,        A0h, Kdim, tid);
        stage32(sb + BOFF, B0h, Kdim, tid);
        if (NT == 3) {
            stage32(sb + TILEB,        A0l, Kdim, tid);
            stage32(sb + BOFF + TILEB, B0l, Kdim, tid);
        }
        CP_COMMIT();
    }

    const int lr = lane & 15;
    const int lcb = (lane >> 4) * 16;   // 0 or 16 within the k16 unit pair

    for (int c = 0; c < nch; c++) {
        if (c + 1 < nch) {
            uint32_t s = sb + ((c + 1) & 1) * STG;
            int k0 = (c + 1) << 5;
            stage32(s,        A0h + k0, Kdim, tid);
            stage32(s + BOFF, B0h + k0, Kdim, tid);
            if (NT == 3) {
                stage32(s + TILEB,        A0l + k0, Kdim, tid);
                stage32(s + BOFF + TILEB, B0l + k0, Kdim, tid);
            }
            CP_COMMIT();
            CP_WAIT1();
        } else {
            CP_WAIT0();
        }
        __syncthreads();

        const uint32_t base = sb + (c & 1) * STG;
#pragma unroll
        for (int s = 0; s < 2; s++) {     // two k16 steps in the 32-k chunk
            const int kb = s * 32 + lcb;
            uint32_t bh[4][2], bl_[4][2];
#pragma unroll
            for (int p = 0; p < 2; p++) {
                uint32_t off = swz64((uint32_t)((wn * 32 + p * 16 + lr) * 64 + kb));
                uint32_t r0, r1, r2, r3;
                LDSM4(r0, r1, r2, r3, base + BOFF + off);
                bh[p * 2][0] = r0; bh[p * 2][1] = r2;
                bh[p * 2 + 1][0] = r1; bh[p * 2 + 1][1] = r3;
                if (NT == 3) {
                    LDSM4(r0, r1, r2, r3, base + BOFF + TILEB + off);
                    bl_[p * 2][0] = r0; bl_[p * 2][1] = r2;
                    bl_[p * 2 + 1][0] = r1; bl_[p * 2 + 1][1] = r3;
                }
            }
#pragma unroll
            for (int f = 0; f < 4; f++) {
                uint32_t off = swz64((uint32_t)((wm * 64 + f * 16 + lr) * 64 + kb));
                uint32_t ah[4];
                LDSM4(ah[0], ah[1], ah[2], ah[3], base + off);
                if (NT == 3) {
                    uint32_t al_[4];
                    LDSM4(al_[0], al_[1], al_[2], al_[3], base + TILEB + off);
#pragma unroll
                    for (int j = 0; j < 4; j++) MMA16816(acc[f][j], ah, bh[j]);
#pragma unroll
                    for (int j = 0; j < 4; j++) MMA16816(acc[f][j], ah, bl_[j]);
#pragma unroll
                    for (int j = 0; j < 4; j++) MMA16816(acc[f][j], al_, bh[j]);
                } else {
#pragma unroll
                    for (int j = 0; j < 4; j++) MMA16816(acc[f][j], ah, bh[j]);
                }
            }
        }
        __syncthreads();
    }

    // ---------------- epilogue ----------------
    const int g = lane >> 2, t = lane & 3;
    if (EPI == 1) {
        // d2 tile -> staging smem, COLUMN-MAJOR tile[c*128 + r] (64 KB exactly);
        // per-thread row scans are then conflict-free.
        float* tile = (float*)smem;
#pragma unroll
        for (int j = 0; j < 4; j++) {
            const int cl = wn * 32 + j * 8 + t * 2;
            const float k0v = extra[n0 + cl];
            const float k1v = extra[n0 + cl + 1];
#pragma unroll
            for (int f = 0; f < 4; f++)
#pragma unroll
                for (int h2 = 0; h2 < 2; h2++) {
                    const int rl = wm * 64 + f * 16 + g + h2 * 8;
                    tile[cl * 128 + rl]       = k0v - 2.0f * acc[f][j][h2 * 2 + 0];
                    tile[(cl + 1) * 128 + rl] = k1v - 2.0f * acc[f][j][h2 * 2 + 1];
                }
        }
        __syncthreads();
        if (tid < 128) {
            const float* rowp = tile + tid;   // element c at rowp[c*128]
            float bv[NKNN]; int bc[NKNN];
#pragma unroll
            for (int r = 0; r < NKNN; r++) { bv[r] = rowp[r * 128]; bc[r] = r; }
            float worst = bv[0]; int ws = 0;
#pragma unroll
            for (int r = 1; r < NKNN; r++)
                if (bv[r] > worst) { worst = bv[r]; ws = r; }
            for (int c = NKNN; c < 128; c++) {
                float v = rowp[c * 128];
                if (v < worst) {
                    bv[ws] = v; bc[ws] = c;
                    worst = bv[0]; ws = 0;
#pragma unroll
                    for (int r = 1; r < NKNN; r++)
                        if (bv[r] > worst) { worst = bv[r]; ws = r; }
                }
            }
            float2* P = (float2*)C;   // already offset by bz*sCz (C in float units)
            float2* op = P + (long long)(m0 + tid) * 256 + blockIdx.x * 16;
#pragma unroll
            for (int r = 0; r < NKNN; r++)
                op[r] = make_float2(bv[r], __int_as_float(n0 + bc[r]));
        }
        return;
    }

    const float rw = (EPI == 3) ? rwp[0] : 0.0f;
#pragma unroll
    for (int f = 0; f < 4; f++) {
        const int row0 = m0 + wm * 64 + f * 16 + g;
#pragma unroll
        for (int j = 0; j < 4; j++) {
            const int col = n0 + wn * 32 + j * 8 + t * 2;
#pragma unroll
            for (int h2 = 0; h2 < 2; h2++) {
                const int row = row0 + h2 * 8;
                float v0 = acc[f][j][h2 * 2 + 0];
                float v1 = acc[f][j][h2 * 2 + 1];
                if (EPI == 2 || EPI == 4) {
                    v0 += bias[col]; v1 += bias[col + 1];
                    if (EPI == 2) {
                        v0 = 0.5f * v0 * (1.0f + erff(v0 * 0.7071067811865476f));
                        v1 = 0.5f * v1 * (1.0f + erff(v1 * 0.7071067811865476f));
                    }
                    __nv_bfloat162 hv;
                    hv.x = __float2bfloat16(v0);
                    hv.y = __float2bfloat16(v1);
                    *(__nv_bfloat162*)(Ch + (long long)row * Ndim + col) = hv;
                } else {
                    if (EPI == 0) { v0 += bias[col]; v1 += bias[col + 1]; }
                    else {
                        long long eidx = (long long)row * Ndim + col;
                        v0 = extra[eidx] + rw * (v0 + bias[col]);
                        v1 = extra[eidx + 1] + rw * (v1 + bias[col + 1]);
                    }
                    *(float2*)(C + (long long)row * Ndim + col) = make_float2(v0, v1);
                }
            }
        }
    }
}

// ---------------- merge 256 partial candidates per row -> top-16 indices -----------
__global__ void __launch_bounds__(256) topk_merge()
{
    int wid = threadIdx.x >> 5, lane = threadIdx.x & 31;
    long long row = (long long)blockIdx.x * 8 + wid;
    const float2* pr = g_part + row * 256;
    float v[8]; int c[8];
#pragma unroll
    for (int s = 0; s < 8; s++) {
        float2 p = pr[lane + 32 * s];
        v[s] = p.x; c[s] = __float_as_int(p.y);
    }
    int* orow = g_idx + row * NKNN;
    for (int r = 0; r < NKNN; r++) {
        float bv = v[0]; int bc = c[0];
#pragma unroll
        for (int s = 1; s < 8; s++)
            if (v[s] < bv || (v[s] == bv && c[s] < bc)) { bv = v[s]; bc = c[s]; }
#pragma unroll
        for (int o = 16; o; o >>= 1) {
            float ov = __shfl_xor_sync(0xffffffffu, bv, o);
            int   oc = __shfl_xor_sync(0xffffffffu, bc, o);
            if (ov < bv || (ov == bv && oc < bc)) { bv = ov; bc = oc; }
        }
#pragma unroll
        for (int s = 0; s < 8; s++)
            if (c[s] == bc) v[s] = FLT_MAX;
        if (lane == 0) orow[r] = bc;
    }
}

// ---------------- f32 -> bf16 hi/lo pair conversion --------------------------------
__global__ void __launch_bounds__(256)
cvt_pair(const float* __restrict__ in, __nv_bfloat16* __restrict__ h,
         __nv_bfloat16* __restrict__ l, int n)
{
    int i = blockIdx.x * 256 + threadIdx.x;
    if (i >= n) return;
    float v = in[i];
    __nv_bfloat16 hh = __float2bfloat16(v);
    h[i] = hh;
    l[i] = __float2bfloat16(v - __bfloat162float(hh));
}

// ---------------- all weight transposes in one launch -------------------------------
__global__ void __launch_bounds__(256)
wconv_all(const float* __restrict__ Wq, const float* __restrict__ Wk,
          const float* __restrict__ Wv, const float* __restrict__ Wo,
          const float* __restrict__ W1, const float* __restrict__ W2)
{
    int i = blockIdx.x * 256 + threadIdx.x;
    const float* W; __nv_bfloat16 *Th, *Tl; int K, N;
    if (i < 32768)       { W = Wq; Th = g_wqkh;             Tl = g_wqkl;             K = DM;  N = DQK; }
    else if (i < 65536)  { W = Wk; Th = g_wqkh + DQK * DM;  Tl = g_wqkl + DQK * DM;  K = DM;  N = DQK; i -= 32768; }
    else if (i < 131072) { W = Wv; Th = g_wvh;  Tl = nullptr; K = DM;  N = DM;  i -= 65536; }
    else if (i < 196608) { W = Wo; Th = g_woh;  Tl = nullptr; K = DM;  N = DM;  i -= 131072; }
    else if (i < 458752) { W = W1; Th = g_w1h;  Tl = nullptr; K = DM;  N = DFF; i -= 196608; }
    else                 { W = W2; Th = g_w2h;  Tl = nullptr; K = DFF; N = DM;  i -= 458752; }
    int k = i / N, n = i % N;
    float v = W[i];
    __nv_bfloat16 h = __float2bfloat16(v);
    Th[(long long)n * K + k] = h;
    if (Tl) Tl[(long long)n * K + k] = __float2bfloat16(v - __bfloat162float(h));
}

// ---------------- bias concat ------------------------------------------------------
__global__ void cat2(const float* __restrict__ a, const float* __restrict__ b,
                     float* __restrict__ o)
{
    int i = threadIdx.x;
    o[i] = (i < DQK) ? a[i] : b[i - DQK];
}

// ---------------- l2 normalize q & k halves of g_qk (in place) + pairs, kk --------
__global__ void __launch_bounds__(256) l2norm_k()
{
    int gw = (blockIdx.x * blockDim.x + threadIdx.x) >> 5;
    int lane = threadIdx.x & 31;
    if (gw >= 2 * MTOK) return;
    bool isq = (gw < MTOK);
    long long rowi = isq ? gw : (gw - MTOK);
    float* base = g_qk + rowi * (2 * DQK) + (isq ? 0 : DQK);
    float4 v = *(float4*)(base + lane * 4);
    float ss = v.x * v.x + v.y * v.y + v.z * v.z + v.w * v.w;
#pragma unroll
    for (int o = 16; o; o >>= 1) ss += __shfl_xor_sync(0xffffffffu, ss, o);
    float inv = 1.0f / fmaxf(sqrtf(ss), 1e-12f);
    v.x *= inv; v.y *= inv; v.z *= inv; v.w *= inv;
    *(float4*)(base + lane * 4) = v;
    __nv_bfloat16* ph = (isq ? g_qph : g_kph) + rowi * DQK + lane * 4;
    __nv_bfloat16* pl = (isq ? g_qpl : g_kpl) + rowi * DQK + lane * 4;
    float e[4] = {v.x, v.y, v.z, v.w};
#pragma unroll
    for (int j = 0; j < 4; j++) {
        __nv_bfloat16 h = __float2bfloat16(e[j]);
        ph[j] = h;
        pl[j] = __float2bfloat16(e[j] - __bfloat162float(h));
    }
    if (!isq) {
        float s2 = v.x * v.x + v.y * v.y + v.z * v.z + v.w * v.w;
#pragma unroll
        for (int o = 16; o; o >>= 1) s2 += __shfl_xor_sync(0xffffffffu, s2, o);
        if (lane == 0) g_kk[rowi] = s2;
    }
}

// ---------------- LayerNorm over D=256 (warp per row) -> bf16 (hi only) ------------
__global__ void __launch_bounds__(256)
ln_k(const float* __restrict__ in, const float* __restrict__ g,
     const float* __restrict__ b, __nv_bfloat16* __restrict__ oh)
{
    int gw = (blockIdx.x * blockDim.x + threadIdx.x) >> 5;
    int lane = threadIdx.x & 31;
    if (gw >= MTOK) return;
    const float* r = in + (long long)gw * DM;
    float4 a0 = *(const float4*)(r + lane * 8);
    float4 a1 = *(const float4*)(r + lane * 8 + 4);
    float s = a0.x + a0.y + a0.z + a0.w + a1.x + a1.y + a1.z + a1.w;
#pragma unroll
    for (int o = 16; o; o >>= 1) s += __shfl_xor_sync(0xffffffffu, s, o);
    float mean = s * (1.0f / 256.0f);
    float d[8] = {a0.x - mean, a0.y - mean, a0.z - mean, a0.w - mean,
                  a1.x - mean, a1.y - mean, a1.z - mean, a1.w - mean};
    float vs = 0.0f;
#pragma unroll
    for (int j = 0; j < 8; j++) vs += d[j] * d[j];
#pragma unroll
    for (int o = 16; o; o >>= 1) vs += __shfl_xor_sync(0xffffffffu, vs, o);
    float is = rsqrtf(vs * (1.0f / 256.0f) + 1e-5f);
    int c = lane * 8;
    long long base = (long long)gw * DM + c;
#pragma unroll
    for (int j = 0; j < 4; j++) {
        __nv_bfloat162 hv;
        hv.x = __float2bfloat16(d[j*2]   * is * g[c + j*2]   + b[c + j*2]);
        hv.y = __float2bfloat16(d[j*2+1] * is * g[c + j*2+1] + b[c + j*2+1]);
        *(__nv_bfloat162*)(oh + base + j * 2) = hv;
    }
}

// ---------------- attention combine (bf16 u gather) -> o as bf16 -------------------
__global__ void __launch_bounds__(256) attn_k()
{
    int t = blockIdx.x * 256 + threadIdx.x;
    int token = t >> 3, h = t & 7;
    if (token >= MTOK) return;
    long long kbase = (long long)(token >> 11) * SEQ;

    const float* qp = g_qk + (long long)token * (2 * DQK) + h * DH;
    float q[16];
#pragma unroll
    for (int i = 0; i < 4; i++)
        *(float4*)&q[i * 4] = *(const float4*)(qp + i * 4);

    const int* ir = g_idx + (long long)token * NKNN;
    int nb[NKNN];
#pragma unroll
    for (int j = 0; j < NKNN; j++) nb[j] = ir[j];

    float lg[NKNN];
#pragma unroll
    for (int j = 0; j < NKNN; j++) {
        const float* kr = g_qk + (kbase + nb[j]) * (2 * DQK) + DQK + h * DH;
        float d = 0.0f;
#pragma unroll
        for (int i = 0; i < 4; i++) {
            float4 kv = *(const float4*)(kr + i * 4);
            d += q[i*4+0]*kv.x + q[i*4+1]*kv.y + q[i*4+2]*kv.z + q[i*4+3]*kv.w;
        }
        lg[j] = d * 0.25f;   // 1/sqrt(16)
    }
    float mx = lg[0];
#pragma unroll
    for (int j = 1; j < NKNN; j++) mx = fmaxf(mx, lg[j]);
    float se = 0.0f;
#pragma unroll
    for (int j = 0; j < NKNN; j++) { lg[j] = expf(lg[j] - mx); se += lg[j]; }
    float inv = 1.0f / se;

    float acc[32];
#pragma unroll
    for (int e = 0; e < 32; e++) acc[e] = 0.0f;
#pragma unroll
    for (int j = 0; j < NKNN; j++) {
        float w = lg[j] * inv;
        const __nv_bfloat16* ur = g_u + (kbase + nb[j]) * DM + h * DV;
#pragma unroll
        for (int i = 0; i < 4; i++) {
            uint4 raw = *(const uint4*)(ur + i * 8);
            const __nv_bfloat162* pp = (const __nv_bfloat162*)&raw;
#pragma unroll
            for (int e = 0; e < 4; e++) {
                float2 f = __bfloat1622float2(pp[e]);
                acc[i*8 + e*2 + 0] += w * f.x;
                acc[i*8 + e*2 + 1] += w * f.y;
            }
        }
    }
    long long obase = (long long)token * DM + h * DV;
#pragma unroll
    for (int e = 0; e < 16; e++) {
        __nv_bfloat162 hv;
        hv.x = __float2bfloat16(acc[e*2]);
        hv.y = __float2bfloat16(acc[e*2+1]);
        *(__nv_bfloat162*)(g_oh + obase + e * 2) = hv;
    }
}

// ---------------- launch sequence ---------------------------------------------------
extern "C" void kernel_launch(void* const* d_in, const int* in_sizes, int n_in,
                              void* d_out, int out_size)
{
    const float* x   = (const float*)d_in[0];
    const float* Wq  = (const float*)d_in[1];
    const float* bq  = (const float*)d_in[2];
    const float* Wk  = (const float*)d_in[3];
    const float* bk  = (const float*)d_in[4];
    const float* Wv  = (const float*)d_in[5];
    const float* bv  = (const float*)d_in[6];
    const float* Wo  = (const float*)d_in[7];
    const float* bo  = (const float*)d_in[8];
    const float* g1v = (const float*)d_in[9];
    const float* b1v = (const float*)d_in[10];
    const float* gf  = (const float*)d_in[11];
    const float* bf  = (const float*)d_in[12];
    const float* W1  = (const float*)d_in[13];
    const float* b1f = (const float*)d_in[14];
    const float* W2  = (const float*)d_in[15];
    const float* b2f = (const float*)d_in[16];
    const float* rw  = (const float*)d_in[17];
    float* out = (float*)d_out;

    const int SM3 = 8 * TILEB;   // 64 KB: 2 stages x 32 KB (3-term)
    const int SM1 = 4 * TILEB;   // 32 KB: 2 stages x 16 KB (1-term)
    cudaFuncSetAttribute(mma_gemm<0, 3>, cudaFuncAttributeMaxDynamicSharedMemorySize, SM3);
    cudaFuncSetAttribute(mma_gemm<1, 3>, cudaFuncAttributeMaxDynamicSharedMemorySize, SM3);
    cudaFuncSetAttribute(mma_gemm<4, 1>, cudaFuncAttributeMaxDynamicSharedMemorySize, SM1);
    cudaFuncSetAttribute(mma_gemm<2, 1>, cudaFuncAttributeMaxDynamicSharedMemorySize, SM1);
    cudaFuncSetAttribute(mma_gemm<3, 1>, cudaFuncAttributeMaxDynamicSharedMemorySize, SM1);

    float *pqk, *pkk, *ppart, *py1, *pbqk;
    cudaGetSymbolAddress((void**)&pqk,  g_qk);
    cudaGetSymbolAddress((void**)&pkk,  g_kk);
    cudaGetSymbolAddress((void**)&ppart, g_part);
    cudaGetSymbolAddress((void**)&py1,  g_y1);
    cudaGetSymbolAddress((void**)&pbqk, g_bqk);

    __nv_bfloat16 *pu, *xh, *xl, *lnh, *qph, *qpl, *kph, *kpl, *oh, *hh;
    __nv_bfloat16 *wqkh, *wqkl, *wvh, *woh, *w1h, *w2h;
    cudaGetSymbolAddress((void**)&pu,  g_u);
    cudaGetSymbolAddress((void**)&xh,  g_xh);  cudaGetSymbolAddress((void**)&xl,  g_xl);
    cudaGetSymbolAddress((void**)&lnh, g_lnh);
    cudaGetSymbolAddress((void**)&qph, g_qph); cudaGetSymbolAddress((void**)&qpl, g_qpl);
    cudaGetSymbolAddress((void**)&kph, g_kph); cudaGetSymbolAddress((void**)&kpl, g_kpl);
    cudaGetSymbolAddress((void**)&oh,  g_oh);
    cudaGetSymbolAddress((void**)&hh,  g_hh);
    cudaGetSymbolAddress((void**)&wqkh, g_wqkh); cudaGetSymbolAddress((void**)&wqkl, g_wqkl);
    cudaGetSymbolAddress((void**)&wvh, g_wvh);
    cudaGetSymbolAddress((void**)&woh, g_woh);
    cudaGetSymbolAddress((void**)&w1h, g_w1h); cudaGetSymbolAddress((void**)&w2h, g_w2h);

    // prep: weight transposes, bias concat, x split
    wconv_all<<<2816, 256>>>(Wq, Wk, Wv, Wo, W1, W2);
    cat2<<<1, 2 * DQK>>>(bq, bk, pbqk);
    cvt_pair<<<(MTOK*DM) / 256, 256>>>(x, xh, xl, MTOK * DM);

    // combined q|k projection (3-term) + l2 normalize
    mma_gemm<0, 3><<<dim3(2, 128, 1), 256, SM3>>>(xh, xl, wqkh, wqkl, pbqk, pqk,
        nullptr, DM, 2 * DQK, nullptr, nullptr, 0, 0, 0, 0);
    l2norm_k<<<4096, 256>>>();

    // fused scores + per-block top-16 partials (no S materialization); then merge
    mma_gemm<1, 3><<<dim3(16, 16, 8), 256, SM3>>>(qph, qpl, kph, kpl, nullptr,
        (float*)ppart, nullptr, DQK, SEQ, pkk, nullptr,
        (long long)SEQ * DQK, (long long)SEQ * DQK,
        (long long)SEQ * 512 /* 256 float2 per row, in float units */,
        (long long)SEQ);
    topk_merge<<<MTOK / 8, 256>>>();

    // u = LN(x) @ Wv + bv   (1-term, bf16 out)
    ln_k<<<2048, 256>>>(x, g1v, b1v, lnh);
    mma_gemm<4, 1><<<dim3(2, 128, 1), 256, SM1>>>(lnh, nullptr, wvh, nullptr, bv, nullptr,
        pu, DM, DM, nullptr, nullptr, 0, 0, 0, 0);
    attn_k<<<512, 256>>>();

    // y1 = x + rw * (o @ Wo + bo)   (1-term)
    mma_gemm<3, 1><<<dim3(2, 128, 1), 256, SM1>>>(oh, nullptr, woh, nullptr, bo, py1,
        nullptr, DM, DM, x, rw, 0, 0, 0, 0);
    // FFN (1-term both)
    ln_k<<<2048, 256>>>(py1, gf, bf, lnh);
    mma_gemm<2, 1><<<dim3(8, 128, 1), 256, SM1>>>(lnh, nullptr, w1h, nullptr, b1f, nullptr,
        hh, DM, DFF, nullptr, nullptr, 0, 0, 0, 0);
    mma_gemm<3, 1><<<dim3(2, 128, 1), 256, SM1>>>(hh, nullptr, w2h, nullptr, b2f, out,
        nullptr, DFF, DM, py1, rw, 0, 0, 0, 0);
}

// round 15
// speedup vs baseline: 1.0201x; 1.0201x over previous
#include <cuda_runtime.h>
#include <cuda_bf16.h>
#include <math.h>
#include <float.h>
#include <stdint.h>

#define BTOT 8
#define SEQ  2048
#define MTOK (BTOT*SEQ)   /* 16384 */
#define DM   256
#define DQK  128
#define NH   8
#define DH   16
#define DV   32
#define NKNN 16
#define DFF  1024

// ---------------- scratch (static device globals; no allocations) ----------------
__device__ float  g_qk [MTOK*2*DQK];     // [tok][0:128]=qn, [128:256]=kn (f32)
__device__ float  g_kk [MTOK];
__device__ float  g_S  [33554432];       // 8 * 2048 * 2048 d2 scores (fp32)
__device__ int    g_idx[MTOK*NKNN];
__device__ float  g_y1 [MTOK*DM];
__device__ float  g_bqk[2*DQK];

// bf16 buffers (hi/lo pairs only where precision-critical)
__device__ __nv_bfloat16 g_u  [MTOK*DM];                  // value rows (bf16)
__device__ __nv_bfloat16 g_xh [MTOK*DM],  g_xl [MTOK*DM];
__device__ __nv_bfloat16 g_lnh[MTOK*DM];
__device__ __nv_bfloat16 g_qph[MTOK*DQK], g_qpl[MTOK*DQK];
__device__ __nv_bfloat16 g_kph[MTOK*DQK], g_kpl[MTOK*DQK];
__device__ __nv_bfloat16 g_oh [MTOK*DM];
__device__ __nv_bfloat16 g_hh [MTOK*DFF];
// transposed weights [N,K] bf16 (q|k keeps lo plane; value-path weights hi only)
__device__ __nv_bfloat16 g_wqkh[2*DQK*DM], g_wqkl[2*DQK*DM];
__device__ __nv_bfloat16 g_wvh[DM*DM];
__device__ __nv_bfloat16 g_woh[DM*DM];
__device__ __nv_bfloat16 g_w1h[DFF*DM];
__device__ __nv_bfloat16 g_w2h[DM*DFF];

// ---------------- PTX helpers -------------------------------------------------------
__device__ __forceinline__ uint32_t smem_u32(const void* p) {
    uint32_t a;
    asm("{ .reg .u64 t; cvta.to.shared.u64 t, %1; cvt.u32.u64 %0, t; }" : "=r"(a) : "l"(p));
    return a;
}
#define LDSM4(r0, r1, r2, r3, a) \
    asm volatile("ldmatrix.sync.aligned.m8n8.x4.shared.b16 {%0,%1,%2,%3}, [%4];" \
                 : "=r"(r0), "=r"(r1), "=r"(r2), "=r"(r3) : "r"(a))
#define MMA16816(c, a, b) \
    asm volatile("mma.sync.aligned.m16n8k16.row.col.f32.bf16.bf16.f32 " \
                 "{%0,%1,%2,%3}, {%4,%5,%6,%7}, {%8,%9}, {%0,%1,%2,%3};" \
                 : "+f"((c)[0]), "+f"((c)[1]), "+f"((c)[2]), "+f"((c)[3]) \
                 : "r"((a)[0]), "r"((a)[1]), "r"((a)[2]), "r"((a)[3]), \
                   "r"((b)[0]), "r"((b)[1]))
#define CP_COMMIT() asm volatile("cp.async.commit_group;" ::: "memory")
#define CP_WAIT1()  asm volatile("cp.async.wait_group 1;" ::: "memory")
#define CP_WAIT0()  asm volatile("cp.async.wait_group 0;" ::: "memory")

// SW64-style swizzle for 64-byte rows
__device__ __forceinline__ uint32_t swz64(uint32_t off) {
    return off ^ ((off >> 3) & 0x30);
}

// stage one 128x32-bf16 tile (64B rows) via cp.async, 256 threads, 2 segs each
__device__ __forceinline__ void stage32(uint32_t dst, const __nv_bfloat16* src,
                                        int ldK, int tid) {
#pragma unroll
    for (int j = 0; j < 2; j++) {
        int u = tid + j * 256;
        int row = u >> 2, seg = u & 3;
        uint32_t off = swz64((uint32_t)(row * 64 + seg * 16));
        const void* gp = (const void*)(src + (long long)row * ldK + seg * 8);
        asm volatile("cp.async.cg.shared.global [%0], [%1], 16;"
                     :: "r"(dst + off), "l"(gp) : "memory");
    }
}

// ---------------- bf16 mma.sync GEMM: C(128x128/blk) = A·Bᵀ, fp32 acc --------------
// A: [M,K] K-major bf16. B: [N,K] K-major bf16. K multiple of 32.
// NT = 3: bf16x3 (ah·bh + ah·bl + al·bh, precision path); NT = 1: plain bf16.
// EPI: 0 = acc+bias -> f32 ; 1 = extra[col]-2*acc -> f32 (d2 scores) ;
//      2 = gelu(acc+bias) -> bf16 ; 3 = extra[row,col]+rw*(acc+bias) -> f32 ;
//      4 = acc+bias -> bf16
// R10-proven engine: 2-stage double buffer, per-f interleaved MMA. DO NOT TOUCH.
#define TILEB 8192

template<int EPI, int NT>
__global__ void __launch_bounds__(256, 2)
mma_gemm(const __nv_bfloat16* __restrict__ Ah, const __nv_bfloat16* __restrict__ Al,
         const __nv_bfloat16* __restrict__ Bh, const __nv_bfloat16* __restrict__ Bl,
         const float* __restrict__ bias, float* __restrict__ C,
         __nv_bfloat16* __restrict__ Ch,
         int Kdim, int Ndim,
         const float* __restrict__ extra, const float* __restrict__ rwp,
         long long sAz, long long sBz, long long sCz, long long sEz)
{
    constexpr uint32_t BOFF = (NT == 3) ? 2 * TILEB : TILEB;       // B tile offset
    constexpr uint32_t STG  = (NT == 3) ? 4 * TILEB : 2 * TILEB;   // stage bytes

    extern __shared__ __align__(128) char smem[];
    const uint32_t sb = smem_u32(smem);
    const int tid = threadIdx.x, lane = tid & 31, wid = tid >> 5;
    const int wm = wid & 1, wn = wid >> 1;
    const int bz = blockIdx.z;
    Ah += bz * sAz; if (NT == 3) Al += bz * sAz;
    Bh += bz * sBz; if (NT == 3) Bl += bz * sBz;
    if (EPI == 0 || EPI == 1 || EPI == 3) C += bz * sCz;
    if (EPI == 1) extra += bz * sEz;
    const int m0 = blockIdx.y * 128, n0 = blockIdx.x * 128;

    const __nv_bfloat16* A0h = Ah + (long long)m0 * Kdim;
    const __nv_bfloat16* A0l = (NT == 3) ? (Al + (long long)m0 * Kdim) : nullptr;
    const __nv_bfloat16* B0h = Bh + (long long)n0 * Kdim;
    const __nv_bfloat16* B0l = (NT == 3) ? (Bl + (long long)n0 * Kdim) : nullptr;

    float acc[4][4][4];
#pragma unroll
    for (int f = 0; f < 4; f++)
#pragma unroll
        for (int j = 0; j < 4; j++)
#pragma unroll
            for (int e = 0; e < 4; e++) acc[f][j][e] = 0.0f;

    const int nch = Kdim >> 5;

    {
        stage32(sb,        A0h, Kdim, tid);
        stage32(sb + BOFF, B0h, Kdim, tid);
        if (NT == 3) {
            stage32(sb + TILEB,        A0l, Kdim, tid);
            stage32(sb + BOFF + TILEB, B0l, Kdim, tid);
        }
        CP_COMMIT();
    }

    const int lr = lane & 15;
    const int lcb = (lane >> 4) * 16;   // 0 or 16 within the k16 unit pair

    for (int c = 0; c < nch; c++) {
        if (c + 1 < nch) {
            uint32_t s = sb + ((c + 1) & 1) * STG;
            int k0 = (c + 1) << 5;
            stage32(s,        A0h + k0, Kdim, tid);
            stage32(s + BOFF, B0h + k0, Kdim, tid);
            if (NT == 3) {
                stage32(s + TILEB,        A0l + k0, Kdim, tid);
                stage32(s + BOFF + TILEB, B0l + k0, Kdim, tid);
            }
            CP_COMMIT();
            CP_WAIT1();
        } else {
            CP_WAIT0();
        }
        __syncthreads();

        const uint32_t base = sb + (c & 1) * STG;
#pragma unroll
        for (int s = 0; s < 2; s++) {     // two k16 steps in the 32-k chunk
            const int kb = s * 32 + lcb;
            uint32_t bh[4][2], bl_[4][2];
#pragma unroll
            for (int p = 0; p < 2; p++) {
                uint32_t off = swz64((uint32_t)((wn * 32 + p * 16 + lr) * 64 + kb));
                uint32_t r0, r1, r2, r3;
                LDSM4(r0, r1, r2, r3, base + BOFF + off);
                bh[p * 2][0] = r0; bh[p * 2][1] = r2;
                bh[p * 2 + 1][0] = r1; bh[p * 2 + 1][1] = r3;
                if (NT == 3) {
                    LDSM4(r0, r1, r2, r3, base + BOFF + TILEB + off);
                    bl_[p * 2][0] = r0; bl_[p * 2][1] = r2;
                    bl_[p * 2 + 1][0] = r1; bl_[p * 2 + 1][1] = r3;
                }
            }
#pragma unroll
            for (int f = 0; f < 4; f++) {
                uint32_t off = swz64((uint32_t)((wm * 64 + f * 16 + lr) * 64 + kb));
                uint32_t ah[4];
                LDSM4(ah[0], ah[1], ah[2], ah[3], base + off);
                if (NT == 3) {
                    uint32_t al_[4];
                    LDSM4(al_[0], al_[1], al_[2], al_[3], base + TILEB + off);
#pragma unroll
                    for (int j = 0; j < 4; j++) MMA16816(acc[f][j], ah, bh[j]);
#pragma unroll
                    for (int j = 0; j < 4; j++) MMA16816(acc[f][j], ah, bl_[j]);
#pragma unroll
                    for (int j = 0; j < 4; j++) MMA16816(acc[f][j], al_, bh[j]);
                } else {
#pragma unroll
                    for (int j = 0; j < 4; j++) MMA16816(acc[f][j], ah, bh[j]);
                }
            }
        }
        __syncthreads();
    }

    // ---------------- epilogue ----------------
    const int g = lane >> 2, t = lane & 3;
    const float rw = (EPI == 3) ? rwp[0] : 0.0f;
#pragma unroll
    for (int f = 0; f < 4; f++) {
        const int row0 = m0 + wm * 64 + f * 16 + g;
#pragma unroll
        for (int j = 0; j < 4; j++) {
            const int col = n0 + wn * 32 + j * 8 + t * 2;
#pragma unroll
            for (int h2 = 0; h2 < 2; h2++) {
                const int row = row0 + h2 * 8;
                float v0 = acc[f][j][h2 * 2 + 0];
                float v1 = acc[f][j][h2 * 2 + 1];
                if (EPI == 2 || EPI == 4) {
                    v0 += bias[col]; v1 += bias[col + 1];
                    if (EPI == 2) {
                        v0 = 0.5f * v0 * (1.0f + erff(v0 * 0.7071067811865476f));
                        v1 = 0.5f * v1 * (1.0f + erff(v1 * 0.7071067811865476f));
                    }
                    __nv_bfloat162 hv;
                    hv.x = __float2bfloat16(v0);
                    hv.y = __float2bfloat16(v1);
                    *(__nv_bfloat162*)(Ch + (long long)row * Ndim + col) = hv;
                } else {
                    if (EPI == 0)      { v0 += bias[col]; v1 += bias[col + 1]; }
                    else if (EPI == 1) {
                        v0 = extra[col] - 2.0f * v0;
                        v1 = extra[col + 1] - 2.0f * v1;
                    } else {
                        long long eidx = (long long)row * Ndim + col;
                        v0 = extra[eidx] + rw * (v0 + bias[col]);
                        v1 = extra[eidx + 1] + rw * (v1 + bias[col + 1]);
                    }
                    *(float2*)(C + (long long)row * Ndim + col) = make_float2(v0, v1);
                }
            }
        }
    }
}

// ---------------- top-16 per score row: per-lane replace-max + merge ---------------
__global__ void __launch_bounds__(256) topk_k()
{
    int wid = threadIdx.x >> 5, lane = threadIdx.x & 31;
    long long row = (long long)blockIdx.x * 8 + wid;
    const float* Sr = g_S + row * SEQ;

    float bv[NKNN]; int bc[NKNN];
#pragma unroll
    for (int j = 0; j < NKNN; j++) { bv[j] = Sr[lane + 32 * j]; bc[j] = lane + 32 * j; }
    float worst = bv[0]; int ws = 0;
#pragma unroll
    for (int j = 1; j < NKNN; j++)
        if (bv[j] > worst) { worst = bv[j]; ws = j; }
#pragma unroll 4
    for (int j = NKNN; j < 64; j++) {
        float v = Sr[lane + 32 * j];
        if (v < worst) {
            bv[ws] = v; bc[ws] = lane + 32 * j;
            worst = bv[0]; ws = 0;
#pragma unroll
            for (int r = 1; r < NKNN; r++)
                if (bv[r] > worst) { worst = bv[r]; ws = r; }
        }
    }

    int* orow = g_idx + row * NKNN;
    for (int r = 0; r < NKNN; r++) {
        float mv = bv[0]; int mc = bc[0]; int ms = 0;
#pragma unroll
        for (int s = 1; s < NKNN; s++)
            if (bv[s] < mv || (bv[s] == mv && bc[s] < mc)) { mv = bv[s]; mc = bc[s]; ms = s; }
        float gv = mv; int gc = mc;
#pragma unroll
        for (int o = 16; o; o >>= 1) {
            float ov = __shfl_xor_sync(0xffffffffu, gv, o);
            int   oc = __shfl_xor_sync(0xffffffffu, gc, o);
            if (ov < gv || (ov == gv && oc < gc)) { gv = ov; gc = oc; }
        }
        if (gc == mc) bv[ms] = FLT_MAX;   // columns are unique -> winner lane only
        if (lane == 0) orow[r] = gc;
    }
}

// ---------------- f32 -> bf16 hi/lo pair conversion --------------------------------
__global__ void __launch_bounds__(256)
cvt_pair(const float* __restrict__ in, __nv_bfloat16* __restrict__ h,
         __nv_bfloat16* __restrict__ l, int n)
{
    int i = blockIdx.x * 256 + threadIdx.x;
    if (i >= n) return;
    float v = in[i];
    __nv_bfloat16 hh = __float2bfloat16(v);
    h[i] = hh;
    l[i] = __float2bfloat16(v - __bfloat162float(hh));
}

// ---------------- all weight transposes in one launch -------------------------------
__global__ void __launch_bounds__(256)
wconv_all(const float* __restrict__ Wq, const float* __restrict__ Wk,
          const float* __restrict__ Wv, const float* __restrict__ Wo,
          const float* __restrict__ W1, const float* __restrict__ W2)
{
    int i = blockIdx.x * 256 + threadIdx.x;
    const float* W; __nv_bfloat16 *Th, *Tl; int K, N;
    if (i < 32768)       { W = Wq; Th = g_wqkh;             Tl = g_wqkl;             K = DM;  N = DQK; }
    else if (i < 65536)  { W = Wk; Th = g_wqkh + DQK * DM;  Tl = g_wqkl + DQK * DM;  K = DM;  N = DQK; i -= 32768; }
    else if (i < 131072) { W = Wv; Th = g_wvh;  Tl = nullptr; K = DM;  N = DM;  i -= 65536; }
    else if (i < 196608) { W = Wo; Th = g_woh;  Tl = nullptr; K = DM;  N = DM;  i -= 131072; }
    else if (i < 458752) { W = W1; Th = g_w1h;  Tl = nullptr; K = DM;  N = DFF; i -= 196608; }
    else                 { W = W2; Th = g_w2h;  Tl = nullptr; K = DFF; N = DM;  i -= 458752; }
    int k = i / N, n = i % N;
    float v = W[i];
    __nv_bfloat16 h = __float2bfloat16(v);
    Th[(long long)n * K + k] = h;
    if (Tl) Tl[(long long)n * K + k] = __float2bfloat16(v - __bfloat162float(h));
}

// ---------------- bias concat ------------------------------------------------------
__global__ void cat2(const float* __restrict__ a, const float* __restrict__ b,
                     float* __restrict__ o)
{
    int i = threadIdx.x;
    o[i] = (i < DQK) ? a[i] : b[i - DQK];
}

// ---------------- l2 normalize q & k halves of g_qk (in place) + pairs, kk --------
__global__ void __launch_bounds__(256) l2norm_k()
{
    int gw = (blockIdx.x * blockDim.x + threadIdx.x) >> 5;
    int lane = threadIdx.x & 31;
    if (gw >= 2 * MTOK) return;
    bool isq = (gw < MTOK);
    long long rowi = isq ? gw : (gw - MTOK);
    float* base = g_qk + rowi * (2 * DQK) + (isq ? 0 : DQK);
    float4 v = *(float4*)(base + lane * 4);
    float ss = v.x * v.x + v.y * v.y + v.z * v.z + v.w * v.w;
#pragma unroll
    for (int o = 16; o; o >>= 1) ss += __shfl_xor_sync(0xffffffffu, ss, o);
    float inv = 1.0f / fmaxf(sqrtf(ss), 1e-12f);
    v.x *= inv; v.y *= inv; v.z *= inv; v.w *= inv;
    *(float4*)(base + lane * 4) = v;
    __nv_bfloat16* ph = (isq ? g_qph : g_kph) + rowi * DQK + lane * 4;
    __nv_bfloat16* pl = (isq ? g_qpl : g_kpl) + rowi * DQK + lane * 4;
    float e[4] = {v.x, v.y, v.z, v.w};
#pragma unroll
    for (int j = 0; j < 4; j++) {
        __nv_bfloat16 h = __float2bfloat16(e[j]);
        ph[j] = h;
        pl[j] = __float2bfloat16(e[j] - __bfloat162float(h));
    }
    if (!isq) {
        float s2 = v.x * v.x + v.y * v.y + v.z * v.z + v.w * v.w;
#pragma unroll
        for (int o = 16; o; o >>= 1) s2 += __shfl_xor_sync(0xffffffffu, s2, o);
        if (lane == 0) g_kk[rowi] = s2;
    }
}

// ---------------- LayerNorm over D=256 (warp per row) -> bf16 (hi only) ------------
__global__ void __launch_bounds__(256)
ln_k(const float* __restrict__ in, const float* __restrict__ g,
     const float* __restrict__ b, __nv_bfloat16* __restrict__ oh)
{
    int gw = (blockIdx.x * blockDim.x + threadIdx.x) >> 5;
    int lane = threadIdx.x & 31;
    if (gw >= MTOK) return;
    const float* r = in + (long long)gw * DM;
    float4 a0 = *(const float4*)(r + lane * 8);
    float4 a1 = *(const float4*)(r + lane * 8 + 4);
    float s = a0.x + a0.y + a0.z + a0.w + a1.x + a1.y + a1.z + a1.w;
#pragma unroll
    for (int o = 16; o; o >>= 1) s += __shfl_xor_sync(0xffffffffu, s, o);
    float mean = s * (1.0f / 256.0f);
    float d[8] = {a0.x - mean, a0.y - mean, a0.z - mean, a0.w - mean,
                  a1.x - mean, a1.y - mean, a1.z - mean, a1.w - mean};
    float vs = 0.0f;
#pragma unroll
    for (int j = 0; j < 8; j++) vs += d[j] * d[j];
#pragma unroll
    for (int o = 16; o; o >>= 1) vs += __shfl_xor_sync(0xffffffffu, vs, o);
    float is = rsqrtf(vs * (1.0f / 256.0f) + 1e-5f);
    int c = lane * 8;
    long long base = (long long)gw * DM + c;
#pragma unroll
    for (int j = 0; j < 4; j++) {
        __nv_bfloat162 hv;
        hv.x = __float2bfloat16(d[j*2]   * is * g[c + j*2]   + b[c + j*2]);
        hv.y = __float2bfloat16(d[j*2+1] * is * g[c + j*2+1] + b[c + j*2+1]);
        *(__nv_bfloat162*)(oh + base + j * 2) = hv;
    }
}

// ---------------- attention combine (bf16 u gather) -> o as bf16 -------------------
__global__ void __launch_bounds__(256) attn_k()
{
    int t = blockIdx.x * 256 + threadIdx.x;
    int token = t >> 3, h = t & 7;
    if (token >= MTOK) return;
    long long kbase = (long long)(token >> 11) * SEQ;

    const float* qp = g_qk + (long long)token * (2 * DQK) + h * DH;
    float q[16];
#pragma unroll
    for (int i = 0; i < 4; i++)
        *(float4*)&q[i * 4] = *(const float4*)(qp + i * 4);

    const int* ir = g_idx + (long long)token * NKNN;
    int nb[NKNN];
#pragma unroll
    for (int j = 0; j < NKNN; j++) nb[j] = ir[j];

    float lg[NKNN];
#pragma unroll
    for (int j = 0; j < NKNN; j++) {
        const float* kr = g_qk + (kbase + nb[j]) * (2 * DQK) + DQK + h * DH;
        float d = 0.0f;
#pragma unroll
        for (int i = 0; i < 4; i++) {
            float4 kv = *(const float4*)(kr + i * 4);
            d += q[i*4+0]*kv.x + q[i*4+1]*kv.y + q[i*4+2]*kv.z + q[i*4+3]*kv.w;
        }
        lg[j] = d * 0.25f;   // 1/sqrt(16)
    }
    float mx = lg[0];
#pragma unroll
    for (int j = 1; j < NKNN; j++) mx = fmaxf(mx, lg[j]);
    float se = 0.0f;
#pragma unroll
    for (int j = 0; j < NKNN; j++) { lg[j] = expf(lg[j] - mx); se += lg[j]; }
    float inv = 1.0f / se;

    float acc[32];
#pragma unroll
    for (int e = 0; e < 32; e++) acc[e] = 0.0f;
#pragma unroll
    for (int j = 0; j < NKNN; j++) {
        float w = lg[j] * inv;
        const __nv_bfloat16* ur = g_u + (kbase + nb[j]) * DM + h * DV;
#pragma unroll
        for (int i = 0; i < 4; i++) {
            uint4 raw = *(const uint4*)(ur + i * 8);
            const __nv_bfloat162* pp = (const __nv_bfloat162*)&raw;
#pragma unroll
            for (int e = 0; e < 4; e++) {
                float2 f = __bfloat1622float2(pp[e]);
                acc[i*8 + e*2 + 0] += w * f.x;
                acc[i*8 + e*2 + 1] += w * f.y;
            }
        }
    }
    long long obase = (long long)token * DM + h * DV;
#pragma unroll
    for (int e = 0; e < 16; e++) {
        __nv_bfloat162 hv;
        hv.x = __float2bfloat16(acc[e*2]);
        hv.y = __float2bfloat16(acc[e*2+1]);
        *(__nv_bfloat162*)(g_oh + obase + e * 2) = hv;
    }
}

// ---------------- launch sequence ---------------------------------------------------
extern "C" void kernel_launch(void* const* d_in, const int* in_sizes, int n_in,
                              void* d_out, int out_size)
{
    const float* x   = (const float*)d_in[0];
    const float* Wq  = (const float*)d_in[1];
    const float* bq  = (const float*)d_in[2];
    const float* Wk  = (const float*)d_in[3];
    const float* bk  = (const float*)d_in[4];
    const float* Wv  = (const float*)d_in[5];
    const float* bv  = (const float*)d_in[6];
    const float* Wo  = (const float*)d_in[7];
    const float* bo  = (const float*)d_in[8];
    const float* g1v = (const float*)d_in[9];
    const float* b1v = (const float*)d_in[10];
    const float* gf  = (const float*)d_in[11];
    const float* bf  = (const float*)d_in[12];
    const float* W1  = (const float*)d_in[13];
    const float* b1f = (const float*)d_in[14];
    const float* W2  = (const float*)d_in[15];
    const float* b2f = (const float*)d_in[16];
    const float* rw  = (const float*)d_in[17];
    float* out = (float*)d_out;

    const int SM3 = 8 * TILEB;   // 64 KB: 2 stages x 32 KB (3-term)
    const int SM1 = 4 * TILEB;   // 32 KB: 2 stages x 16 KB (1-term)
    cudaFuncSetAttribute(mma_gemm<0, 3>, cudaFuncAttributeMaxDynamicSharedMemorySize, SM3);
    cudaFuncSetAttribute(mma_gemm<1, 3>, cudaFuncAttributeMaxDynamicSharedMemorySize, SM3);
    cudaFuncSetAttribute(mma_gemm<4, 1>, cudaFuncAttributeMaxDynamicSharedMemorySize, SM1);
    cudaFuncSetAttribute(mma_gemm<2, 1>, cudaFuncAttributeMaxDynamicSharedMemorySize, SM1);
    cudaFuncSetAttribute(mma_gemm<3, 1>, cudaFuncAttributeMaxDynamicSharedMemorySize, SM1);

    float *pqk, *pkk, *pS, *py1, *pbqk;
    cudaGetSymbolAddress((void**)&pqk,  g_qk);
    cudaGetSymbolAddress((void**)&pkk,  g_kk);
    cudaGetSymbolAddress((void**)&pS,   g_S);
    cudaGetSymbolAddress((void**)&py1,  g_y1);
    cudaGetSymbolAddress((void**)&pbqk, g_bqk);

    __nv_bfloat16 *pu, *xh, *xl, *lnh, *qph, *qpl, *kph, *kpl, *oh, *hh;
    __nv_bfloat16 *wqkh, *wqkl, *wvh, *woh, *w1h, *w2h;
    cudaGetSymbolAddress((void**)&pu,  g_u);
    cudaGetSymbolAddress((void**)&xh,  g_xh);  cudaGetSymbolAddress((void**)&xl,  g_xl);
    cudaGetSymbolAddress((void**)&lnh, g_lnh);
    cudaGetSymbolAddress((void**)&qph, g_qph); cudaGetSymbolAddress((void**)&qpl, g_qpl);
    cudaGetSymbolAddress((void**)&kph, g_kph); cudaGetSymbolAddress((void**)&kpl, g_kpl);
    cudaGetSymbolAddress((void**)&oh,  g_oh);
    cudaGetSymbolAddress((void**)&hh,  g_hh);
    cudaGetSymbolAddress((void**)&wqkh, g_wqkh); cudaGetSymbolAddress((void**)&wqkl, g_wqkl);
    cudaGetSymbolAddress((void**)&wvh, g_wvh);
    cudaGetSymbolAddress((void**)&woh, g_woh);
    cudaGetSymbolAddress((void**)&w1h, g_w1h); cudaGetSymbolAddress((void**)&w2h, g_w2h);

    // prep: weight transposes, bias concat, x split
    wconv_all<<<2816, 256>>>(Wq, Wk, Wv, Wo, W1, W2);
    cat2<<<1, 2 * DQK>>>(bq, bk, pbqk);
    cvt_pair<<<(MTOK*DM) / 256, 256>>>(x, xh, xl, MTOK * DM);

    // combined q|k projection (3-term) + l2 normalize
    mma_gemm<0, 3><<<dim3(2, 128, 1), 256, SM3>>>(xh, xl, wqkh, wqkl, pbqk, pqk,
        nullptr, DM, 2 * DQK, nullptr, nullptr, 0, 0, 0, 0);
    l2norm_k<<<4096, 256>>>();

    // scores S = kk[col] - 2 qn·kn^T -> f32 (unchunked) + topk
    mma_gemm<1, 3><<<dim3(16, 16, 8), 256, SM3>>>(qph, qpl, kph, kpl, nullptr, pS,
        nullptr, DQK, SEQ, pkk, nullptr,
        (long long)SEQ * DQK, (long long)SEQ * DQK,
        (long long)SEQ * SEQ, (long long)SEQ);
    topk_k<<<MTOK / 8, 256>>>();

    // u = LN(x) @ Wv + bv   (1-term, bf16 out)
    ln_k<<<2048, 256>>>(x, g1v, b1v, lnh);
    mma_gemm<4, 1><<<dim3(2, 128, 1), 256, SM1>>>(lnh, nullptr, wvh, nullptr, bv, nullptr,
        pu, DM, DM, nullptr, nullptr, 0, 0, 0, 0);
    attn_k<<<512, 256>>>();

    // y1 = x + rw * (o @ Wo + bo)   (1-term)
    mma_gemm<3, 1><<<dim3(2, 128, 1), 256, SM1>>>(oh, nullptr, woh, nullptr, bo, py1,
        nullptr, DM, DM, x, rw, 0, 0, 0, 0);
    // FFN (1-term both)
    ln_k<<<2048, 256>>>(py1, gf, bf, lnh);
    mma_gemm<2, 1><<<dim3(8, 128, 1), 256, SM1>>>(lnh, nullptr, w1h, nullptr, b1f, nullptr,
        hh, DM, DFF, nullptr, nullptr, 0, 0, 0, 0);
    mma_gemm<3, 1><<<dim3(2, 128, 1), 256, SM1>>>(hh, nullptr, w2h, nullptr, b2f, out,
        nullptr, DFF, DM, py1, rw, 0, 0, 0, 0);
}

// round 16
// speedup vs baseline: 1.0986x; 1.0770x over previous
#include <cuda_runtime.h>
#include <cuda_bf16.h>
#include <math.h>
#include <float.h>
#include <stdint.h>

#define BTOT 8
#define SEQ  2048
#define MTOK (BTOT*SEQ)   /* 16384 */
#define DM   256
#define DQK  128
#define NH   8
#define DH   16
#define DV   32
#define NKNN 16
#define DFF  1024

// ---------------- scratch (static device globals; no allocations) ----------------
__device__ float  g_qk [MTOK*2*DQK];     // [tok][0:128]=qn, [128:256]=kn (f32)
__device__ float  g_kk [MTOK];
__device__ float  g_S  [33554432];       // 8 * 2048 * 2048 d2 scores (fp32)
__device__ int    g_idx[MTOK*NKNN];
__device__ float  g_y1 [MTOK*DM];
__device__ float  g_bqk[2*DQK];

// bf16 buffers (hi/lo pairs only where precision-critical)
__device__ __nv_bfloat16 g_u  [MTOK*DM];                  // value rows (bf16)
__device__ __nv_bfloat16 g_xh [MTOK*DM],  g_xl [MTOK*DM];
__device__ __nv_bfloat16 g_lnh[MTOK*DM];
__device__ __nv_bfloat16 g_qph[MTOK*DQK];                 // q hi only (2-term score)
__device__ __nv_bfloat16 g_kph[MTOK*DQK], g_kpl[MTOK*DQK];
__device__ __nv_bfloat16 g_oh [MTOK*DM];
__device__ __nv_bfloat16 g_hh [MTOK*DFF];
// transposed weights [N,K] bf16 (q|k keeps lo plane; value-path weights hi only)
__device__ __nv_bfloat16 g_wqkh[2*DQK*DM], g_wqkl[2*DQK*DM];
__device__ __nv_bfloat16 g_wvh[DM*DM];
__device__ __nv_bfloat16 g_woh[DM*DM];
__device__ __nv_bfloat16 g_w1h[DFF*DM];
__device__ __nv_bfloat16 g_w2h[DM*DFF];

// ---------------- PTX helpers -------------------------------------------------------
__device__ __forceinline__ uint32_t smem_u32(const void* p) {
    uint32_t a;
    asm("{ .reg .u64 t; cvta.to.shared.u64 t, %1; cvt.u32.u64 %0, t; }" : "=r"(a) : "l"(p));
    return a;
}
#define LDSM4(r0, r1, r2, r3, a) \
    asm volatile("ldmatrix.sync.aligned.m8n8.x4.shared.b16 {%0,%1,%2,%3}, [%4];" \
                 : "=r"(r0), "=r"(r1), "=r"(r2), "=r"(r3) : "r"(a))
#define MMA16816(c, a, b) \
    asm volatile("mma.sync.aligned.m16n8k16.row.col.f32.bf16.bf16.f32 " \
                 "{%0,%1,%2,%3}, {%4,%5,%6,%7}, {%8,%9}, {%0,%1,%2,%3};" \
                 : "+f"((c)[0]), "+f"((c)[1]), "+f"((c)[2]), "+f"((c)[3]) \
                 : "r"((a)[0]), "r"((a)[1]), "r"((a)[2]), "r"((a)[3]), \
                   "r"((b)[0]), "r"((b)[1]))
#define CP_COMMIT() asm volatile("cp.async.commit_group;" ::: "memory")
#define CP_WAIT1()  asm volatile("cp.async.wait_group 1;" ::: "memory")
#define CP_WAIT0()  asm volatile("cp.async.wait_group 0;" ::: "memory")

// SW64-style swizzle for 64-byte rows
__device__ __forceinline__ uint32_t swz64(uint32_t off) {
    return off ^ ((off >> 3) & 0x30);
}

// stage one 128x32-bf16 tile (64B rows) via cp.async, 256 threads, 2 segs each
__device__ __forceinline__ void stage32(uint32_t dst, const __nv_bfloat16* src,
                                        int ldK, int tid) {
#pragma unroll
    for (int j = 0; j < 2; j++) {
        int u = tid + j * 256;
        int row = u >> 2, seg = u & 3;
        uint32_t off = swz64((uint32_t)(row * 64 + seg * 16));
        const void* gp = (const void*)(src + (long long)row * ldK + seg * 8);
        asm volatile("cp.async.cg.shared.global [%0], [%1], 16;"
                     :: "r"(dst + off), "l"(gp) : "memory");
    }
}

// ---------------- bf16 mma.sync GEMM: C(128x128/blk) = A·Bᵀ, fp32 acc --------------
// A: [M,K] K-major bf16. B: [N,K] K-major bf16. K multiple of 32.
// NT = 3: bf16x3 (ah·bh + ah·bl + al·bh); NT = 2: ah·bh + ah·bl (A hi only);
// NT = 1: plain bf16.
// EPI: 0 = acc+bias -> f32 ; 1 = extra[col]-2*acc -> f32 (d2 scores) ;
//      2 = gelu(acc+bias) -> bf16 ; 3 = extra[row,col]+rw*(acc+bias) -> f32 ;
//      4 = acc+bias -> bf16
// R10-proven engine: 2-stage double buffer, per-f interleaved MMA. DO NOT TOUCH.
#define TILEB 8192

template<int EPI, int NT>
__global__ void __launch_bounds__(256, 2)
mma_gemm(const __nv_bfloat16* __restrict__ Ah, const __nv_bfloat16* __restrict__ Al,
         const __nv_bfloat16* __restrict__ Bh, const __nv_bfloat16* __restrict__ Bl,
         const float* __restrict__ bias, float* __restrict__ C,
         __nv_bfloat16* __restrict__ Ch,
         int Kdim, int Ndim,
         const float* __restrict__ extra, const float* __restrict__ rwp,
         long long sAz, long long sBz, long long sCz, long long sEz)
{
    // tile layout per stage: Ah @0; [Al @TILEB if NT==3]; Bh @BH_OFF; [Bl @BL_OFF if NT>=2]
    constexpr uint32_t BH_OFF = (NT == 3) ? 2 * TILEB : TILEB;
    constexpr uint32_t BL_OFF = BH_OFF + TILEB;
    constexpr uint32_t STG    = (NT == 3) ? 4 * TILEB : (NT == 2 ? 3 * TILEB : 2 * TILEB);

    extern __shared__ __align__(128) char smem[];
    const uint32_t sb = smem_u32(smem);
    const int tid = threadIdx.x, lane = tid & 31, wid = tid >> 5;
    const int wm = wid & 1, wn = wid >> 1;
    const int bz = blockIdx.z;
    Ah += bz * sAz; if (NT == 3) Al += bz * sAz;
    Bh += bz * sBz; if (NT >= 2) Bl += bz * sBz;
    if (EPI == 0 || EPI == 1 || EPI == 3) C += bz * sCz;
    if (EPI == 1) extra += bz * sEz;
    const int m0 = blockIdx.y * 128, n0 = blockIdx.x * 128;

    const __nv_bfloat16* A0h = Ah + (long long)m0 * Kdim;
    const __nv_bfloat16* A0l = (NT == 3) ? (Al + (long long)m0 * Kdim) : nullptr;
    const __nv_bfloat16* B0h = Bh + (long long)n0 * Kdim;
    const __nv_bfloat16* B0l = (NT >= 2) ? (Bl + (long long)n0 * Kdim) : nullptr;

    float acc[4][4][4];
#pragma unroll
    for (int f = 0; f < 4; f++)
#pragma unroll
        for (int j = 0; j < 4; j++)
#pragma unroll
            for (int e = 0; e < 4; e++) acc[f][j][e] = 0.0f;

    const int nch = Kdim >> 5;

    {
        stage32(sb,          A0h, Kdim, tid);
        stage32(sb + BH_OFF, B0h, Kdim, tid);
        if (NT == 3) stage32(sb + TILEB,  A0l, Kdim, tid);
        if (NT >= 2) stage32(sb + BL_OFF, B0l, Kdim, tid);
        CP_COMMIT();
    }

    const int lr = lane & 15;
    const int lcb = (lane >> 4) * 16;   // 0 or 16 within the k16 unit pair

    for (int c = 0; c < nch; c++) {
        if (c + 1 < nch) {
            uint32_t s = sb + ((c + 1) & 1) * STG;
            int k0 = (c + 1) << 5;
            stage32(s,          A0h + k0, Kdim, tid);
            stage32(s + BH_OFF, B0h + k0, Kdim, tid);
            if (NT == 3) stage32(s + TILEB,  A0l + k0, Kdim, tid);
            if (NT >= 2) stage32(s + BL_OFF, B0l + k0, Kdim, tid);
            CP_COMMIT();
            CP_WAIT1();
        } else {
            CP_WAIT0();
        }
        __syncthreads();

        const uint32_t base = sb + (c & 1) * STG;
#pragma unroll
        for (int s = 0; s < 2; s++) {     // two k16 steps in the 32-k chunk
            const int kb = s * 32 + lcb;
            uint32_t bh[4][2], bl_[4][2];
#pragma unroll
            for (int p = 0; p < 2; p++) {
                uint32_t off = swz64((uint32_t)((wn * 32 + p * 16 + lr) * 64 + kb));
                uint32_t r0, r1, r2, r3;
                LDSM4(r0, r1, r2, r3, base + BH_OFF + off);
                bh[p * 2][0] = r0; bh[p * 2][1] = r2;
                bh[p * 2 + 1][0] = r1; bh[p * 2 + 1][1] = r3;
                if (NT >= 2) {
                    LDSM4(r0, r1, r2, r3, base + BL_OFF + off);
                    bl_[p * 2][0] = r0; bl_[p * 2][1] = r2;
                    bl_[p * 2 + 1][0] = r1; bl_[p * 2 + 1][1] = r3;
                }
            }
#pragma unroll
            for (int f = 0; f < 4; f++) {
                uint32_t off = swz64((uint32_t)((wm * 64 + f * 16 + lr) * 64 + kb));
                uint32_t ah[4];
                LDSM4(ah[0], ah[1], ah[2], ah[3], base + off);
                if (NT == 3) {
                    uint32_t al_[4];
                    LDSM4(al_[0], al_[1], al_[2], al_[3], base + TILEB + off);
#pragma unroll
                    for (int j = 0; j < 4; j++) MMA16816(acc[f][j], ah, bh[j]);
#pragma unroll
                    for (int j = 0; j < 4; j++) MMA16816(acc[f][j], ah, bl_[j]);
#pragma unroll
                    for (int j = 0; j < 4; j++) MMA16816(acc[f][j], al_, bh[j]);
                } else if (NT == 2) {
#pragma unroll
                    for (int j = 0; j < 4; j++) MMA16816(acc[f][j], ah, bh[j]);
#pragma unroll
                    for (int j = 0; j < 4; j++) MMA16816(acc[f][j], ah, bl_[j]);
                } else {
#pragma unroll
                    for (int j = 0; j < 4; j++) MMA16816(acc[f][j], ah, bh[j]);
                }
            }
        }
        __syncthreads();
    }

    // ---------------- epilogue ----------------
    const int g = lane >> 2, t = lane & 3;
    const float rw = (EPI == 3) ? rwp[0] : 0.0f;
#pragma unroll
    for (int f = 0; f < 4; f++) {
        const int row0 = m0 + wm * 64 + f * 16 + g;
#pragma unroll
        for (int j = 0; j < 4; j++) {
            const int col = n0 + wn * 32 + j * 8 + t * 2;
#pragma unroll
            for (int h2 = 0; h2 < 2; h2++) {
                const int row = row0 + h2 * 8;
                float v0 = acc[f][j][h2 * 2 + 0];
                float v1 = acc[f][j][h2 * 2 + 1];
                if (EPI == 2 || EPI == 4) {
                    v0 += bias[col]; v1 += bias[col + 1];
                    if (EPI == 2) {
                        v0 = 0.5f * v0 * (1.0f + erff(v0 * 0.7071067811865476f));
                        v1 = 0.5f * v1 * (1.0f + erff(v1 * 0.7071067811865476f));
                    }
                    __nv_bfloat162 hv;
                    hv.x = __float2bfloat16(v0);
                    hv.y = __float2bfloat16(v1);
                    *(__nv_bfloat162*)(Ch + (long long)row * Ndim + col) = hv;
                } else {
                    if (EPI == 0)      { v0 += bias[col]; v1 += bias[col + 1]; }
                    else if (EPI == 1) {
                        v0 = extra[col] - 2.0f * v0;
                        v1 = extra[col + 1] - 2.0f * v1;
                    } else {
                        long long eidx = (long long)row * Ndim + col;
                        v0 = extra[eidx] + rw * (v0 + bias[col]);
                        v1 = extra[eidx + 1] + rw * (v1 + bias[col + 1]);
                    }
                    *(float2*)(C + (long long)row * Ndim + col) = make_float2(v0, v1);
                }
            }
        }
    }
}

// ---------------- top-16 per score row: per-lane replace-max + merge ---------------
__global__ void __launch_bounds__(256) topk_k()
{
    int wid = threadIdx.x >> 5, lane = threadIdx.x & 31;
    long long row = (long long)blockIdx.x * 8 + wid;
    const float* Sr = g_S + row * SEQ;

    float bv[NKNN]; int bc[NKNN];
#pragma unroll
    for (int j = 0; j < NKNN; j++) { bv[j] = Sr[lane + 32 * j]; bc[j] = lane + 32 * j; }
    float worst = bv[0]; int ws = 0;
#pragma unroll
    for (int j = 1; j < NKNN; j++)
        if (bv[j] > worst) { worst = bv[j]; ws = j; }
#pragma unroll 4
    for (int j = NKNN; j < 64; j++) {
        float v = Sr[lane + 32 * j];
        if (v < worst) {
            bv[ws] = v; bc[ws] = lane + 32 * j;
            worst = bv[0]; ws = 0;
#pragma unroll
            for (int r = 1; r < NKNN; r++)
                if (bv[r] > worst) { worst = bv[r]; ws = r; }
        }
    }

    int* orow = g_idx + row * NKNN;
    for (int r = 0; r < NKNN; r++) {
        float mv = bv[0]; int mc = bc[0]; int ms = 0;
#pragma unroll
        for (int s = 1; s < NKNN; s++)
            if (bv[s] < mv || (bv[s] == mv && bc[s] < mc)) { mv = bv[s]; mc = bc[s]; ms = s; }
        float gv = mv; int gc = mc;
#pragma unroll
        for (int o = 16; o; o >>= 1) {
            float ov = __shfl_xor_sync(0xffffffffu, gv, o);
            int   oc = __shfl_xor_sync(0xffffffffu, gc, o);
            if (ov < gv || (ov == gv && oc < gc)) { gv = ov; gc = oc; }
        }
        if (gc == mc) bv[ms] = FLT_MAX;   // columns are unique -> winner lane only
        if (lane == 0) orow[r] = gc;
    }
}

// ---------------- f32 -> bf16 hi/lo pair conversion --------------------------------
__global__ void __launch_bounds__(256)
cvt_pair(const float* __restrict__ in, __nv_bfloat16* __restrict__ h,
         __nv_bfloat16* __restrict__ l, int n)
{
    int i = blockIdx.x * 256 + threadIdx.x;
    if (i >= n) return;
    float v = in[i];
    __nv_bfloat16 hh = __float2bfloat16(v);
    h[i] = hh;
    l[i] = __float2bfloat16(v - __bfloat162float(hh));
}

// ---------------- all weight transposes in one launch -------------------------------
__global__ void __launch_bounds__(256)
wconv_all(const float* __restrict__ Wq, const float* __restrict__ Wk,
          const float* __restrict__ Wv, const float* __restrict__ Wo,
          const float* __restrict__ W1, const float* __restrict__ W2)
{
    int i = blockIdx.x * 256 + threadIdx.x;
    const float* W; __nv_bfloat16 *Th, *Tl; int K, N;
    if (i < 32768)       { W = Wq; Th = g_wqkh;             Tl = g_wqkl;             K = DM;  N = DQK; }
    else if (i < 65536)  { W = Wk; Th = g_wqkh + DQK * DM;  Tl = g_wqkl + DQK * DM;  K = DM;  N = DQK; i -= 32768; }
    else if (i < 131072) { W = Wv; Th = g_wvh;  Tl = nullptr; K = DM;  N = DM;  i -= 65536; }
    else if (i < 196608) { W = Wo; Th = g_woh;  Tl = nullptr; K = DM;  N = DM;  i -= 131072; }
    else if (i < 458752) { W = W1; Th = g_w1h;  Tl = nullptr; K = DM;  N = DFF; i -= 196608; }
    else                 { W = W2; Th = g_w2h;  Tl = nullptr; K = DFF; N = DM;  i -= 458752; }
    int k = i / N, n = i % N;
    float v = W[i];
    __nv_bfloat16 h = __float2bfloat16(v);
    Th[(long long)n * K + k] = h;
    if (Tl) Tl[(long long)n * K + k] = __float2bfloat16(v - __bfloat162float(h));
}

// ---------------- bias concat ------------------------------------------------------
__global__ void cat2(const float* __restrict__ a, const float* __restrict__ b,
                     float* __restrict__ o)
{
    int i = threadIdx.x;
    o[i] = (i < DQK) ? a[i] : b[i - DQK];
}

// ---------------- l2 normalize q & k halves of g_qk (in place) + bf16 planes, kk ---
// q: hi only (2-term score uses q-hi); k: hi + lo pair.
__global__ void __launch_bounds__(256) l2norm_k()
{
    int gw = (blockIdx.x * blockDim.x + threadIdx.x) >> 5;
    int lane = threadIdx.x & 31;
    if (gw >= 2 * MTOK) return;
    bool isq = (gw < MTOK);
    long long rowi = isq ? gw : (gw - MTOK);
    float* base = g_qk + rowi * (2 * DQK) + (isq ? 0 : DQK);
    float4 v = *(float4*)(base + lane * 4);
    float ss = v.x * v.x + v.y * v.y + v.z * v.z + v.w * v.w;
#pragma unroll
    for (int o = 16; o; o >>= 1) ss += __shfl_xor_sync(0xffffffffu, ss, o);
    float inv = 1.0f / fmaxf(sqrtf(ss), 1e-12f);
    v.x *= inv; v.y *= inv; v.z *= inv; v.w *= inv;
    *(float4*)(base + lane * 4) = v;
    float e[4] = {v.x, v.y, v.z, v.w};
    if (isq) {
        __nv_bfloat16* ph = g_qph + rowi * DQK + lane * 4;
#pragma unroll
        for (int j = 0; j < 4; j++) ph[j] = __float2bfloat16(e[j]);
    } else {
        __nv_bfloat16* ph = g_kph + rowi * DQK + lane * 4;
        __nv_bfloat16* pl = g_kpl + rowi * DQK + lane * 4;
#pragma unroll
        for (int j = 0; j < 4; j++) {
            __nv_bfloat16 h = __float2bfloat16(e[j]);
            ph[j] = h;
            pl[j] = __float2bfloat16(e[j] - __bfloat162float(h));
        }
        float s2 = v.x * v.x + v.y * v.y + v.z * v.z + v.w * v.w;
#pragma unroll
        for (int o = 16; o; o >>= 1) s2 += __shfl_xor_sync(0xffffffffu, s2, o);
        if (lane == 0) g_kk[rowi] = s2;
    }
}

// ---------------- LayerNorm over D=256 (warp per row) -> bf16 (hi only) ------------
__global__ void __launch_bounds__(256)
ln_k(const float* __restrict__ in, const float* __restrict__ g,
     const float* __restrict__ b, __nv_bfloat16* __restrict__ oh)
{
    int gw = (blockIdx.x * blockDim.x + threadIdx.x) >> 5;
    int lane = threadIdx.x & 31;
    if (gw >= MTOK) return;
    const float* r = in + (long long)gw * DM;
    float4 a0 = *(const float4*)(r + lane * 8);
    float4 a1 = *(const float4*)(r + lane * 8 + 4);
    float s = a0.x + a0.y + a0.z + a0.w + a1.x + a1.y + a1.z + a1.w;
#pragma unroll
    for (int o = 16; o; o >>= 1) s += __shfl_xor_sync(0xffffffffu, s, o);
    float mean = s * (1.0f / 256.0f);
    float d[8] = {a0.x - mean, a0.y - mean, a0.z - mean, a0.w - mean,
                  a1.x - mean, a1.y - mean, a1.z - mean, a1.w - mean};
    float vs = 0.0f;
#pragma unroll
    for (int j = 0; j < 8; j++) vs += d[j] * d[j];
#pragma unroll
    for (int o = 16; o; o >>= 1) vs += __shfl_xor_sync(0xffffffffu, vs, o);
    float is = rsqrtf(vs * (1.0f / 256.0f) + 1e-5f);
    int c = lane * 8;
    long long base = (long long)gw * DM + c;
#pragma unroll
    for (int j = 0; j < 4; j++) {
        __nv_bfloat162 hv;
        hv.x = __float2bfloat16(d[j*2]   * is * g[c + j*2]   + b[c + j*2]);
        hv.y = __float2bfloat16(d[j*2+1] * is * g[c + j*2+1] + b[c + j*2+1]);
        *(__nv_bfloat162*)(oh + base + j * 2) = hv;
    }
}

// ---------------- attention combine (bf16 q/k/u gathers) -> o as bf16 --------------
__global__ void __launch_bounds__(256) attn_k()
{
    int t = blockIdx.x * 256 + threadIdx.x;
    int token = t >> 3, h = t & 7;
    if (token >= MTOK) return;
    long long kbase = (long long)(token >> 11) * SEQ;

    // q head slice from bf16 plane (16 bf16 = 32 B)
    const __nv_bfloat16* qp = g_qph + (long long)token * DQK + h * DH;
    float q[16];
    {
        uint4 r0 = *(const uint4*)qp;
        uint4 r1 = *(const uint4*)(qp + 8);
        const __nv_bfloat162* p0 = (const __nv_bfloat162*)&r0;
        const __nv_bfloat162* p1 = (const __nv_bfloat162*)&r1;
#pragma unroll
        for (int e = 0; e < 4; e++) {
            float2 f = __bfloat1622float2(p0[e]);
            q[e*2] = f.x; q[e*2+1] = f.y;
        }
#pragma unroll
        for (int e = 0; e < 4; e++) {
            float2 f = __bfloat1622float2(p1[e]);
            q[8+e*2] = f.x; q[8+e*2+1] = f.y;
        }
    }

    const int* ir = g_idx + (long long)token * NKNN;
    int nb[NKNN];
#pragma unroll
    for (int j = 0; j < NKNN; j++) nb[j] = ir[j];

    float lg[NKNN];
#pragma unroll
    for (int j = 0; j < NKNN; j++) {
        const __nv_bfloat16* kr = g_kph + (kbase + nb[j]) * DQK + h * DH;
        uint4 r0 = *(const uint4*)kr;
        uint4 r1 = *(const uint4*)(kr + 8);
        const __nv_bfloat162* p0 = (const __nv_bfloat162*)&r0;
        const __nv_bfloat162* p1 = (const __nv_bfloat162*)&r1;
        float d = 0.0f;
#pragma unroll
        for (int e = 0; e < 4; e++) {
            float2 f = __bfloat1622float2(p0[e]);
            d += q[e*2] * f.x + q[e*2+1] * f.y;
        }
#pragma unroll
        for (int e = 0; e < 4; e++) {
            float2 f = __bfloat1622float2(p1[e]);
            d += q[8+e*2] * f.x + q[8+e*2+1] * f.y;
        }
        lg[j] = d * 0.25f;   // 1/sqrt(16)
    }
    float mx = lg[0];
#pragma unroll
    for (int j = 1; j < NKNN; j++) mx = fmaxf(mx, lg[j]);
    float se = 0.0f;
#pragma unroll
    for (int j = 0; j < NKNN; j++) { lg[j] = expf(lg[j] - mx); se += lg[j]; }
    float inv = 1.0f / se;

    float acc[32];
#pragma unroll
    for (int e = 0; e < 32; e++) acc[e] = 0.0f;
#pragma unroll
    for (int j = 0; j < NKNN; j++) {
        float w = lg[j] * inv;
        const __nv_bfloat16* ur = g_u + (kbase + nb[j]) * DM + h * DV;
#pragma unroll
        for (int i = 0; i < 4; i++) {
            uint4 raw = *(const uint4*)(ur + i * 8);
            const __nv_bfloat162* pp = (const __nv_bfloat162*)&raw;
#pragma unroll
            for (int e = 0; e < 4; e++) {
                float2 f = __bfloat1622float2(pp[e]);
                acc[i*8 + e*2 + 0] += w * f.x;
                acc[i*8 + e*2 + 1] += w * f.y;
            }
        }
    }
    long long obase = (long long)token * DM + h * DV;
#pragma unroll
    for (int e = 0; e < 16; e++) {
        __nv_bfloat162 hv;
        hv.x = __float2bfloat16(acc[e*2]);
        hv.y = __float2bfloat16(acc[e*2+1]);
        *(__nv_bfloat162*)(g_oh + obase + e * 2) = hv;
    }
}

// ---------------- launch sequence ---------------------------------------------------
extern "C" void kernel_launch(void* const* d_in, const int* in_sizes, int n_in,
                              void* d_out, int out_size)
{
    const float* x   = (const float*)d_in[0];
    const float* Wq  = (const float*)d_in[1];
    const float* bq  = (const float*)d_in[2];
    const float* Wk  = (const float*)d_in[3];
    const float* bk  = (const float*)d_in[4];
    const float* Wv  = (const float*)d_in[5];
    const float* bv  = (const float*)d_in[6];
    const float* Wo  = (const float*)d_in[7];
    const float* bo  = (const float*)d_in[8];
    const float* g1v = (const float*)d_in[9];
    const float* b1v = (const float*)d_in[10];
    const float* gf  = (const float*)d_in[11];
    const float* bf  = (const float*)d_in[12];
    const float* W1  = (const float*)d_in[13];
    const float* b1f = (const float*)d_in[14];
    const float* W2  = (const float*)d_in[15];
    const float* b2f = (const float*)d_in[16];
    const float* rw  = (const float*)d_in[17];
    float* out = (float*)d_out;

    const int SM3 = 8 * TILEB;   // 64 KB: 2 stages x 32 KB (3-term)
    const int SM2 = 6 * TILEB;   // 48 KB: 2 stages x 24 KB (2-term)
    const int SM1 = 4 * TILEB;   // 32 KB: 2 stages x 16 KB (1-term)
    cudaFuncSetAttribute(mma_gemm<0, 3>, cudaFuncAttributeMaxDynamicSharedMemorySize, SM3);
    cudaFuncSetAttribute(mma_gemm<1, 2>, cudaFuncAttributeMaxDynamicSharedMemorySize, SM2);
    cudaFuncSetAttribute(mma_gemm<4, 1>, cudaFuncAttributeMaxDynamicSharedMemorySize, SM1);
    cudaFuncSetAttribute(mma_gemm<2, 1>, cudaFuncAttributeMaxDynamicSharedMemorySize, SM1);
    cudaFuncSetAttribute(mma_gemm<3, 1>, cudaFuncAttributeMaxDynamicSharedMemorySize, SM1);

    float *pqk, *pkk, *pS, *py1, *pbqk;
    cudaGetSymbolAddress((void**)&pqk,  g_qk);
    cudaGetSymbolAddress((void**)&pkk,  g_kk);
    cudaGetSymbolAddress((void**)&pS,   g_S);
    cudaGetSymbolAddress((void**)&py1,  g_y1);
    cudaGetSymbolAddress((void**)&pbqk, g_bqk);

    __nv_bfloat16 *pu, *xh, *xl, *lnh, *qph, *kph, *kpl, *oh, *hh;
    __nv_bfloat16 *wqkh, *wqkl, *wvh, *woh, *w1h, *w2h;
    cudaGetSymbolAddress((void**)&pu,  g_u);
    cudaGetSymbolAddress((void**)&xh,  g_xh);  cudaGetSymbolAddress((void**)&xl,  g_xl);
    cudaGetSymbolAddress((void**)&lnh, g_lnh);
    cudaGetSymbolAddress((void**)&qph, g_qph);
    cudaGetSymbolAddress((void**)&kph, g_kph); cudaGetSymbolAddress((void**)&kpl, g_kpl);
    cudaGetSymbolAddress((void**)&oh,  g_oh);
    cudaGetSymbolAddress((void**)&hh,  g_hh);
    cudaGetSymbolAddress((void**)&wqkh, g_wqkh); cudaGetSymbolAddress((void**)&wqkl, g_wqkl);
    cudaGetSymbolAddress((void**)&wvh, g_wvh);
    cudaGetSymbolAddress((void**)&woh, g_woh);
    cudaGetSymbolAddress((void**)&w1h, g_w1h); cudaGetSymbolAddress((void**)&w2h, g_w2h);

    // prep: weight transposes, bias concat, x split
    wconv_all<<<2816, 256>>>(Wq, Wk, Wv, Wo, W1, W2);
    cat2<<<1, 2 * DQK>>>(bq, bk, pbqk);
    cvt_pair<<<(MTOK*DM) / 256, 256>>>(x, xh, xl, MTOK * DM);

    // combined q|k projection (3-term) + l2 normalize
    mma_gemm<0, 3><<<dim3(2, 128, 1), 256, SM3>>>(xh, xl, wqkh, wqkl, pbqk, pqk,
        nullptr, DM, 2 * DQK, nullptr, nullptr, 0, 0, 0, 0);
    l2norm_k<<<4096, 256>>>();

    // scores S = kk[col] - 2 qh·(kh+kl)^T -> f32 (2-term) + topk
    mma_gemm<1, 2><<<dim3(16, 16, 8), 256, SM2>>>(qph, nullptr, kph, kpl, nullptr, pS,
        nullptr, DQK, SEQ, pkk, nullptr,
        (long long)SEQ * DQK, (long long)SEQ * DQK,
        (long long)SEQ * SEQ, (long long)SEQ);
    topk_k<<<MTOK / 8, 256>>>();

    // u = LN(x) @ Wv + bv   (1-term, bf16 out)
    ln_k<<<2048, 256>>>(x, g1v, b1v, lnh);
    mma_gemm<4, 1><<<dim3(2, 128, 1), 256, SM1>>>(lnh, nullptr, wvh, nullptr, bv, nullptr,
        pu, DM, DM, nullptr, nullptr, 0, 0, 0, 0);
    attn_k<<<512, 256>>>();

    // y1 = x + rw * (o @ Wo + bo)   (1-term)
    mma_gemm<3, 1><<<dim3(2, 128, 1), 256, SM1>>>(oh, nullptr, woh, nullptr, bo, py1,
        nullptr, DM, DM, x, rw, 0, 0, 0, 0);
    // FFN (1-term both)
    ln_k<<<2048, 256>>>(py1, gf, bf, lnh);
    mma_gemm<2, 1><<<dim3(8, 128, 1), 256, SM1>>>(lnh, nullptr, w1h, nullptr, b1f, nullptr,
        hh, DM, DFF, nullptr, nullptr, 0, 0, 0, 0);
    mma_gemm<3, 1><<<dim3(2, 128, 1), 256, SM1>>>(hh, nullptr, w2h, nullptr, b2f, out,
        nullptr, DFF, DM, py1, rw, 0, 0, 0, 0);
}